// round 2
// baseline (speedup 1.0000x reference)
#include <cuda_runtime.h>
#include <math.h>

// Problem constants
#define NP   100000      // primal nodes
#define EPn  1600000     // primal edges
#define NDU  1600000     // dual nodes
#define EDU  3200000     // dual edges
#define EPT  (EPn + NP)  // primal edges + self loops
#define EDT  (EDU + NDU) // dual edges + self loops
#define NEG_SLOPE 0.2f

// -------- static device scratch (no allocations allowed) --------
__device__ int   g_pcnt[NP], g_poff[NP], g_pfill[NP];
__device__ int   g_dcnt[NDU], g_doff[NDU], g_dfill[NDU];
__device__ int   g_psrc[EPT];
__device__ int   g_dsrc[EDT];
__device__ int   g_cursor[2];
__device__ float g_dinv[NDU];
__device__ float g_h[NP * 64];      // x @ W1
__device__ float g_as1[NP * 8], g_ad1[NP * 8];
__device__ float g_helu[NP * 64];   // elu(GAT1 out)
__device__ float g_as2[NP], g_ad2[NP];
__device__ float g_q1[NDU * 8];     // relu(GCN1 out)
__device__ float g_vs[64], g_vd[64]; // W2 @ att_src2 / att_dst2

__device__ __forceinline__ float leaky(float e) { return e > 0.f ? e : NEG_SLOPE * e; }

// ---------------- CSR construction ----------------
__global__ void k_zero() {
    int i = blockIdx.x * blockDim.x + threadIdx.x;
    if (i < NDU) g_dcnt[i] = 0;
    if (i < NP)  g_pcnt[i] = 0;
    if (i == 0) { g_cursor[0] = 0; g_cursor[1] = 0; }
}

__global__ void k_hist_p(const int* __restrict__ ei) {
    int i = blockIdx.x * blockDim.x + threadIdx.x;
    if (i >= EPT) return;
    int dst = (i < EPn) ? ei[EPn + i] : (i - EPn);
    atomicAdd(&g_pcnt[dst], 1);
}
__global__ void k_hist_d(const int* __restrict__ ei) {
    int i = blockIdx.x * blockDim.x + threadIdx.x;
    if (i >= EDT) return;
    int dst = (i < EDU) ? ei[EDU + i] : (i - EDU);
    atomicAdd(&g_dcnt[dst], 1);
}

// Block-aggregated exclusive scan -> per-node offsets. One atomic per BLOCK.
// NOTE: globals are bound in DEVICE code (passing __device__ symbols as host-side
// kernel args is illegal and was the Round-1 correctness bug).
__device__ __forceinline__ void alloc_body(const int* __restrict__ cnt,
                                           int* __restrict__ off,
                                           int* __restrict__ fill,
                                           int n, int curIdx, int doDinv) {
    __shared__ int sh[1024];
    __shared__ int base;
    int t = threadIdx.x;
    int i = blockIdx.x * 1024 + t;
    int v = (i < n) ? cnt[i] : 0;
    sh[t] = v;
    __syncthreads();
    #pragma unroll
    for (int d = 1; d < 1024; d <<= 1) {
        int add = (t >= d) ? sh[t - d] : 0;
        __syncthreads();
        sh[t] += add;
        __syncthreads();
    }
    if (t == 1023) base = atomicAdd(&g_cursor[curIdx], sh[1023]);
    __syncthreads();
    if (i < n) {
        int o = base + sh[t] - v;   // exclusive
        off[i] = o;
        fill[i] = o;
        if (doDinv) g_dinv[i] = rsqrtf((float)(v > 0 ? v : 1));
    }
}
__global__ void k_alloc_p() { alloc_body(g_pcnt, g_poff, g_pfill, NP, 0, 0); }
__global__ void k_alloc_d() { alloc_body(g_dcnt, g_doff, g_dfill, NDU, 1, 1); }

__global__ void k_fill_p(const int* __restrict__ ei) {
    int i = blockIdx.x * blockDim.x + threadIdx.x;
    if (i >= EPT) return;
    int src, dst;
    if (i < EPn) { src = ei[i]; dst = ei[EPn + i]; }
    else         { src = dst = i - EPn; }
    int pos = atomicAdd(&g_pfill[dst], 1);
    g_psrc[pos] = src;
}
__global__ void k_fill_d(const int* __restrict__ ei) {
    int i = blockIdx.x * blockDim.x + threadIdx.x;
    if (i >= EDT) return;
    int src, dst;
    if (i < EDU) { src = ei[i]; dst = ei[EDU + i]; }
    else         { src = dst = i - EDU; }
    int pos = atomicAdd(&g_dfill[dst], 1);
    g_dsrc[pos] = src;
}

// ---------------- GEMM: h = x @ W1  (100000x512 @ 512x64) ----------------
__global__ __launch_bounds__(256) void k_gemm1(const float* __restrict__ x,
                                               const float* __restrict__ W) {
    __shared__ __align__(16) float Xs[64][17];
    __shared__ __align__(16) float Ws[16][64];
    int tid = threadIdx.x;
    int tx = tid & 15, ty = tid >> 4;
    int row0 = blockIdx.x * 64;
    float acc[4][4] = {};
    for (int k0 = 0; k0 < 512; k0 += 16) {
        // X tile: 64 rows x 16 k (one float4 per thread)
        int r = tid >> 2, c4 = (tid & 3) * 4;
        float4 xv = make_float4(0.f, 0.f, 0.f, 0.f);
        if (row0 + r < NP)
            xv = *(const float4*)&x[(row0 + r) * 512 + k0 + c4];
        Xs[r][c4] = xv.x; Xs[r][c4 + 1] = xv.y; Xs[r][c4 + 2] = xv.z; Xs[r][c4 + 3] = xv.w;
        // W tile: 16 k x 64 cols
        int kr = tid >> 4, cc = (tid & 15) * 4;
        *(float4*)&Ws[kr][cc] = *(const float4*)&W[(k0 + kr) * 64 + cc];
        __syncthreads();
        #pragma unroll
        for (int kk = 0; kk < 16; kk++) {
            float a[4], b[4];
            #pragma unroll
            for (int i = 0; i < 4; i++) a[i] = Xs[ty * 4 + i][kk];
            #pragma unroll
            for (int j = 0; j < 4; j++) b[j] = Ws[kk][tx * 4 + j];
            #pragma unroll
            for (int i = 0; i < 4; i++)
                #pragma unroll
                for (int j = 0; j < 4; j++)
                    acc[i][j] = fmaf(a[i], b[j], acc[i][j]);
        }
        __syncthreads();
    }
    #pragma unroll
    for (int i = 0; i < 4; i++) {
        int row = row0 + ty * 4 + i;
        if (row < NP)
            *(float4*)&g_h[row * 64 + tx * 4] =
                make_float4(acc[i][0], acc[i][1], acc[i][2], acc[i][3]);
    }
}

// per-node attention logits for layer 1
__global__ void k_alpha1(const float* __restrict__ att_s, const float* __restrict__ att_d) {
    int n = blockIdx.x * blockDim.x + threadIdx.x;
    if (n >= NP) return;
    #pragma unroll
    for (int h = 0; h < 8; h++) {
        float ss = 0.f, dd = 0.f;
        #pragma unroll
        for (int k = 0; k < 8; k++) {
            float v = g_h[n * 64 + h * 8 + k];
            ss = fmaf(v, __ldg(&att_s[h * 8 + k]), ss);
            dd = fmaf(v, __ldg(&att_d[h * 8 + k]), dd);
        }
        g_as1[n * 8 + h] = ss;
        g_ad1[n * 8 + h] = dd;
    }
}

// vs = W2 @ att_src2, vd = W2 @ att_dst2   (64 threads)
__global__ void k_vsvd(const float* __restrict__ W2,
                       const float* __restrict__ as2, const float* __restrict__ ad2) {
    int c = threadIdx.x;
    if (c >= 64) return;
    float s = 0.f, d = 0.f;
    #pragma unroll
    for (int j = 0; j < 16; j++) {
        float w = W2[c * 16 + j];
        s = fmaf(w, __ldg(&as2[j]), s);
        d = fmaf(w, __ldg(&ad2[j]), d);
    }
    g_vs[c] = s;
    g_vd[c] = d;
}

// ---------------- GAT layer 1: warp per dst, segment softmax + weighted sum ----------------
__global__ __launch_bounds__(256) void k_gat1(const float* __restrict__ b1) {
    int warp = (blockIdx.x * blockDim.x + threadIdx.x) >> 5;
    int lane = threadIdx.x & 31;
    if (warp >= NP) return;
    int dst = warp;
    int s = g_poff[dst], cnt = g_pcnt[dst];
    int head = lane >> 2, lig = lane & 3;   // 4 lanes per head
    float adv = g_ad1[dst * 8 + head];
    // pass 1: per-head max
    float m = -1e30f;
    for (int j = s + lig; j < s + cnt; j += 4) {
        int src = g_psrc[j];
        m = fmaxf(m, leaky(g_as1[src * 8 + head] + adv));
    }
    m = fmaxf(m, __shfl_xor_sync(0xffffffffu, m, 1));
    m = fmaxf(m, __shfl_xor_sync(0xffffffffu, m, 2));
    // pass 2: per-head denom
    float den = 0.f;
    for (int j = s + lig; j < s + cnt; j += 4) {
        int src = g_psrc[j];
        den += __expf(leaky(g_as1[src * 8 + head] + adv) - m);
    }
    den += __shfl_xor_sync(0xffffffffu, den, 1);
    den += __shfl_xor_sync(0xffffffffu, den, 2);
    float inv = 1.0f / (den + 1e-16f);
    // pass 3: weighted sum (each lane owns 2 channels of the same head)
    int c0 = lane * 2;
    float a0 = 0.f, a1 = 0.f;
    for (int j = s; j < s + cnt; j++) {
        int src = g_psrc[j];
        float w = __expf(leaky(g_as1[src * 8 + head] + adv) - m);
        float2 hv = *(const float2*)&g_h[src * 64 + c0];
        a0 = fmaf(w, hv.x, a0);
        a1 = fmaf(w, hv.y, a1);
    }
    a0 = a0 * inv + __ldg(&b1[c0]);
    a1 = a1 * inv + __ldg(&b1[c0 + 1]);
    a0 = a0 > 0.f ? a0 : (__expf(a0) - 1.f);   // ELU
    a1 = a1 > 0.f ? a1 : (__expf(a1) - 1.f);
    *(float2*)&g_helu[dst * 64 + c0] = make_float2(a0, a1);
    // fused layer-2 logits: as2[dst] = h_elu . vs, ad2 = h_elu . vd
    float ss = a0 * g_vs[c0] + a1 * g_vs[c0 + 1];
    float dd = a0 * g_vd[c0] + a1 * g_vd[c0 + 1];
    #pragma unroll
    for (int o = 16; o > 0; o >>= 1) {
        ss += __shfl_xor_sync(0xffffffffu, ss, o);
        dd += __shfl_xor_sync(0xffffffffu, dd, o);
    }
    if (lane == 0) { g_as2[dst] = ss; g_ad2[dst] = dd; }
}

// ---------------- GAT layer 2: warp per dst, heads=1; matmul hoisted after aggregation ----------------
__global__ __launch_bounds__(256) void k_gat2(const float* __restrict__ W2,
                                              const float* __restrict__ b2,
                                              float* __restrict__ out) {
    __shared__ float W2s[64 * 16];
    __shared__ float accs[8][64];
    for (int i = threadIdx.x; i < 64 * 16; i += blockDim.x) W2s[i] = W2[i];
    __syncthreads();
    int warp = (blockIdx.x * blockDim.x + threadIdx.x) >> 5;
    int lane = threadIdx.x & 31;
    int wip = (threadIdx.x >> 5);
    if (warp >= NP) return;
    int dst = warp;
    int s = g_poff[dst], cnt = g_pcnt[dst];
    float adv = g_ad2[dst];
    float m = -1e30f;
    for (int j = s + lane; j < s + cnt; j += 32)
        m = fmaxf(m, leaky(g_as2[g_psrc[j]] + adv));
    #pragma unroll
    for (int o = 16; o > 0; o >>= 1) m = fmaxf(m, __shfl_xor_sync(0xffffffffu, m, o));
    float den = 0.f;
    for (int j = s + lane; j < s + cnt; j += 32)
        den += __expf(leaky(g_as2[g_psrc[j]] + adv) - m);
    #pragma unroll
    for (int o = 16; o > 0; o >>= 1) den += __shfl_xor_sync(0xffffffffu, den, o);
    float inv = 1.0f / (den + 1e-16f);
    int c0 = lane * 2;
    float a0 = 0.f, a1 = 0.f;
    for (int j = s; j < s + cnt; j++) {
        int src = g_psrc[j];
        float w = __expf(leaky(g_as2[src] + adv) - m);
        float2 hv = *(const float2*)&g_helu[src * 64 + c0];
        a0 = fmaf(w, hv.x, a0);
        a1 = fmaf(w, hv.y, a1);
    }
    accs[wip][c0] = a0 * inv;
    accs[wip][c0 + 1] = a1 * inv;
    __syncwarp();
    if (lane < 16) {
        float o = __ldg(&b2[lane]);
        #pragma unroll
        for (int c = 0; c < 64; c++) o = fmaf(accs[wip][c], W2s[c * 16 + lane], o);
        out[dst * 16 + lane] = o;
    }
}

// ---------------- dual GCN layers: thread per dst; matmul hoisted after aggregation ----------------
__global__ void k_gcn1(const float* __restrict__ dx, const float* __restrict__ Wg1,
                       const float* __restrict__ bg1) {
    int n = blockIdx.x * blockDim.x + threadIdx.x;
    if (n >= NDU) return;
    int s = g_doff[n], cnt = g_dcnt[n];
    float di = g_dinv[n];
    float4 acc = make_float4(0.f, 0.f, 0.f, 0.f);
    for (int j = s; j < s + cnt; j++) {
        int src = g_dsrc[j];
        float nr = di * g_dinv[src];
        float4 v = *(const float4*)&dx[src * 4];
        acc.x = fmaf(nr, v.x, acc.x); acc.y = fmaf(nr, v.y, acc.y);
        acc.z = fmaf(nr, v.z, acc.z); acc.w = fmaf(nr, v.w, acc.w);
    }
    float o[8];
    #pragma unroll
    for (int j = 0; j < 8; j++) {
        float v = __ldg(&bg1[j]);
        v = fmaf(acc.x, __ldg(&Wg1[0 * 8 + j]), v);
        v = fmaf(acc.y, __ldg(&Wg1[1 * 8 + j]), v);
        v = fmaf(acc.z, __ldg(&Wg1[2 * 8 + j]), v);
        v = fmaf(acc.w, __ldg(&Wg1[3 * 8 + j]), v);
        o[j] = v > 0.f ? v : 0.f;   // ReLU
    }
    *(float4*)&g_q1[n * 8]     = make_float4(o[0], o[1], o[2], o[3]);
    *(float4*)&g_q1[n * 8 + 4] = make_float4(o[4], o[5], o[6], o[7]);
}

__global__ void k_gcn2(const float* __restrict__ Wg2, const float* __restrict__ bg2,
                       float* __restrict__ qout) {
    int n = blockIdx.x * blockDim.x + threadIdx.x;
    if (n >= NDU) return;
    int s = g_doff[n], cnt = g_dcnt[n];
    float di = g_dinv[n];
    float acc[8] = {};
    for (int j = s; j < s + cnt; j++) {
        int src = g_dsrc[j];
        float nr = di * g_dinv[src];
        float4 q0 = *(const float4*)&g_q1[src * 8];
        float4 q1 = *(const float4*)&g_q1[src * 8 + 4];
        acc[0] = fmaf(nr, q0.x, acc[0]); acc[1] = fmaf(nr, q0.y, acc[1]);
        acc[2] = fmaf(nr, q0.z, acc[2]); acc[3] = fmaf(nr, q0.w, acc[3]);
        acc[4] = fmaf(nr, q1.x, acc[4]); acc[5] = fmaf(nr, q1.y, acc[5]);
        acc[6] = fmaf(nr, q1.z, acc[6]); acc[7] = fmaf(nr, q1.w, acc[7]);
    }
    #pragma unroll
    for (int j4 = 0; j4 < 4; j4++) {
        float4 ov;
        float* op = (float*)&ov;
        #pragma unroll
        for (int t = 0; t < 4; t++) {
            int j = j4 * 4 + t;
            float v = __ldg(&bg2[j]);
            #pragma unroll
            for (int i = 0; i < 8; i++) v = fmaf(acc[i], __ldg(&Wg2[i * 16 + j]), v);
            op[t] = v;
        }
        *(float4*)&qout[n * 16 + j4 * 4] = ov;
    }
}

// ---------------- launcher ----------------
extern "C" void kernel_launch(void* const* d_in, const int* in_sizes, int n_in,
                              void* d_out, int out_size) {
    const float* x    = (const float*)d_in[0];
    const int*   ei   = (const int*)d_in[1];
    const float* dx   = (const float*)d_in[2];
    const int*   dei  = (const int*)d_in[3];
    const float* W1   = (const float*)d_in[4];
    const float* as1  = (const float*)d_in[5];
    const float* ad1  = (const float*)d_in[6];
    const float* b1   = (const float*)d_in[7];
    const float* W2   = (const float*)d_in[8];
    const float* as2  = (const float*)d_in[9];
    const float* ad2  = (const float*)d_in[10];
    const float* b2   = (const float*)d_in[11];
    const float* Wg1  = (const float*)d_in[12];
    const float* bg1  = (const float*)d_in[13];
    const float* Wg2  = (const float*)d_in[14];
    const float* bg2  = (const float*)d_in[15];
    float* out = (float*)d_out;              // [NP,16] then [NDU,16]
    float* qout = out + (size_t)NP * 16;

    // CSR build
    k_zero<<<(NDU + 255) / 256, 256>>>();
    k_hist_p<<<(EPT + 255) / 256, 256>>>(ei);
    k_hist_d<<<(EDT + 255) / 256, 256>>>(dei);
    k_alloc_p<<<(NP + 1023) / 1024, 1024>>>();
    k_alloc_d<<<(NDU + 1023) / 1024, 1024>>>();
    k_fill_p<<<(EPT + 255) / 256, 256>>>(ei);
    k_fill_d<<<(EDT + 255) / 256, 256>>>(dei);

    // primal GAT branch
    k_gemm1<<<(NP + 63) / 64, 256>>>(x, W1);
    k_alpha1<<<(NP + 255) / 256, 256>>>(as1, ad1);
    k_vsvd<<<1, 64>>>(W2, as2, ad2);
    k_gat1<<<(NP * 32 + 255) / 256, 256>>>(b1);
    k_gat2<<<(NP * 32 + 255) / 256, 256>>>(W2, b2, out);

    // dual GCN branch
    k_gcn1<<<(NDU + 255) / 256, 256>>>(dx, Wg1, bg1);
    k_gcn2<<<(NDU + 255) / 256, 256>>>(Wg2, bg2, qout);
}